// round 10
// baseline (speedup 1.0000x reference)
#include <cuda_runtime.h>
#include <cuda_fp16.h>
#include <math.h>
#include <stdint.h>

#define D 1024
#define F 4096
#define MTOT 8192

typedef __half fp16;

// ---- scratch (static device globals: allocation-free) ----
__device__ fp16 g_x16[(size_t)MTOT * D];  // 16 MB
__device__ fp16 g_wfc[(size_t)F * D];     // 8 MB
__device__ fp16 g_h16[(size_t)MTOT * F];  // 64 MB
__device__ fp16 g_wp[(size_t)D * F];      // 8 MB
__device__ unsigned int g_max2[2];

// ===========================================================================
// helpers
// ===========================================================================
__device__ __forceinline__ uint32_t smem_u32(const void* p) {
    uint32_t a;
    asm("{ .reg .u64 t; cvta.to.shared.u64 t, %1; cvt.u32.u64 %0, t; }" : "=r"(a) : "l"(p));
    return a;
}
__device__ __forceinline__ void cp16(uint32_t s, const void* g) {
    asm volatile("cp.async.cg.shared.global [%0], [%1], 16;" :: "r"(s), "l"(g));
}
__device__ __forceinline__ void cp_commit() {
    asm volatile("cp.async.commit_group;");
}
__device__ __forceinline__ void cp_wait1() {
    asm volatile("cp.async.wait_group 1;");
}
__device__ __forceinline__ void ldsm4(uint32_t a, uint32_t* r) {
    asm volatile("ldmatrix.sync.aligned.m8n8.x4.shared.b16 {%0,%1,%2,%3}, [%4];"
                 : "=r"(r[0]), "=r"(r[1]), "=r"(r[2]), "=r"(r[3]) : "r"(a));
}
__device__ __forceinline__ void mma16816(float* c, const uint32_t* a, uint32_t b0, uint32_t b1) {
    asm volatile(
        "mma.sync.aligned.m16n8k16.row.col.f32.f16.f16.f32 "
        "{%0,%1,%2,%3}, {%4,%5,%6,%7}, {%8,%9}, {%0,%1,%2,%3};"
        : "+f"(c[0]), "+f"(c[1]), "+f"(c[2]), "+f"(c[3])
        : "r"(a[0]), "r"(a[1]), "r"(a[2]), "r"(a[3]), "r"(b0), "r"(b1));
}

// ===========================================================================
// pre-pass kernels
// ===========================================================================
__global__ void k_init_max() { g_max2[0] = 0u; g_max2[1] = 0u; }

// blockIdx.y selects tensor (0: W_fc, 1: W_proj); both are F*D floats.
__global__ void k_absmax2(const float* __restrict__ W0, const float* __restrict__ W1) {
    int sel = blockIdx.y;
    const float* W = sel ? W1 : W0;
    int n = F * D;
    float m = 0.f;
    int stride = gridDim.x * blockDim.x;
    for (int i = blockIdx.x * blockDim.x + threadIdx.x; i < n; i += stride)
        m = fmaxf(m, fabsf(W[i]));
    #pragma unroll
    for (int o = 16; o; o >>= 1) m = fmaxf(m, __shfl_xor_sync(0xffffffffu, m, o));
    __shared__ float sm[8];
    int lane = threadIdx.x & 31, w = threadIdx.x >> 5;
    if (lane == 0) sm[w] = m;
    __syncthreads();
    if (threadIdx.x == 0) {
        float mm = sm[0];
        for (int i = 1; i < 8; i++) mm = fmaxf(mm, sm[i]);
        atomicMax(&g_max2[sel], __float_as_uint(mm));
    }
}

// fakequant(W) + 2*B@A -> single fp16, row-major [out, K]
__global__ void k_quant_w(const float* __restrict__ W, const float* __restrict__ A,
                          const float* __restrict__ Bm, fp16* __restrict__ Wo,
                          int K, int sel) {
    int o = blockIdx.y;
    __shared__ float Bs[16];
    if (threadIdx.x < 16) Bs[threadIdx.x] = Bm[o * 16 + threadIdx.x];
    __syncthreads();
    float mx = __uint_as_float(g_max2[sel]);
    float scale = mx * (1.0f / 127.0f);
    float inv   = 127.0f / mx;
    int k = (blockIdx.x * blockDim.x + threadIdx.x) * 2;
    float w0 = W[(size_t)o * K + k], w1 = W[(size_t)o * K + k + 1];
    float q0 = fminf(fmaxf(rintf(w0 * inv), -128.f), 127.f) * scale;
    float q1 = fminf(fmaxf(rintf(w1 * inv), -128.f), 127.f) * scale;
    float a0 = 0.f, a1 = 0.f;
    #pragma unroll
    for (int r = 0; r < 16; r++) {
        a0 = fmaf(Bs[r], A[(size_t)r * K + k],     a0);
        a1 = fmaf(Bs[r], A[(size_t)r * K + k + 1], a1);
    }
    float v0 = q0 + 2.0f * a0, v1 = q1 + 2.0f * a1;
    *(__half2*)(Wo + (size_t)o * K + k) = __floats2half2_rn(v0, v1);
}

__global__ void k_convert_x(const float4* __restrict__ x, fp16* __restrict__ xo) {
    size_t i = (size_t)blockIdx.x * blockDim.x + threadIdx.x;
    float4 v = x[i];
    __half2* p = (__half2*)(xo + i * 4);
    p[0] = __floats2half2_rn(v.x, v.y);
    p[1] = __floats2half2_rn(v.z, v.w);
}

// ===========================================================================
// GEMM: C[M,N] = A[M,K] * B[N,K]^T + bias, pure fp16, fp32 accum
// CTA 128x256, BK=64, SW128-swizzled smem (128B rows, no pad), 3-stage
// cp.async ring, ONE barrier per iteration, register-double-buffered ldsm.
// 8 warps = 2(m) x 4(n), warp tile 64x64.
// ===========================================================================
#define BK 64
#define MAT_A (128 * 128)             // 16384
#define MAT_Bm (256 * 128)            // 32768
#define STAGE_B (MAT_A + MAT_Bm)      // 49152
#define NSTAGE 3
#define GSMEM (NSTAGE * STAGE_B)      // 147456

template <int MODE>
__global__ void __launch_bounds__(256, 1)
k_gemm(const fp16* __restrict__ Ax, const fp16* __restrict__ Bw,
       const float* __restrict__ bias, float* __restrict__ outf,
       fp16* __restrict__ outH, int K, int N) {
    extern __shared__ char smem[];
    uint32_t sb = smem_u32(smem);
    int tid = threadIdx.x, wid = tid >> 5, lane = tid & 31;
    int m0 = blockIdx.y * 128;
    int n0 = blockIdx.x * 256;
    int warp_m = (wid >> 2) * 64;
    int warp_n = (wid & 3) * 64;

    float acc[4][8][4];
    #pragma unroll
    for (int i = 0; i < 4; i++)
        #pragma unroll
        for (int j = 0; j < 8; j++)
            #pragma unroll
            for (int q = 0; q < 4; q++) acc[i][j][q] = 0.f;

    int KT = K / BK;

    // ldmatrix address components (swizzle XOR precomputed per fragment row)
    uint32_t cb = (uint32_t)((lane >> 4) * 16);    // 16B half-select
    uint32_t a_r[4], a_x[4], b_r[4], b_x[4];
    #pragma unroll
    for (int mi = 0; mi < 4; mi++) {
        int row = warp_m + mi * 16 + (lane & 15);
        a_r[mi] = (uint32_t)(row * 128);
        a_x[mi] = (uint32_t)((row & 7) << 4);
    }
    #pragma unroll
    for (int g = 0; g < 4; g++) {
        int row = warp_n + g * 16 + (lane & 15);
        b_r[g] = (uint32_t)(MAT_A + row * 128);
        b_x[g] = (uint32_t)((row & 7) << 4);
    }

    // cp.async mapping. A: 128 rows x 8 chunks; thread t -> row t>>1, 4 chunks.
    int a_row = tid >> 1;
    uint32_t a_half = (uint32_t)((tid & 1) * 64);
    uint32_t a_sw[4];
    #pragma unroll
    for (int i = 0; i < 4; i++)
        a_sw[i] = (uint32_t)(a_row * 128) + ((a_half + i * 16) ^ ((a_row & 7) << 4));
    // B: 256 rows x 8 chunks; thread t -> row t, 8 chunks.
    uint32_t b_sw[8];
    #pragma unroll
    for (int j = 0; j < 8; j++)
        b_sw[j] = (uint32_t)(MAT_A + tid * 128) + (uint32_t)((j * 16) ^ ((tid & 7) << 4));

    auto load_stage = [&](int slot, int kt) {
        uint32_t st = sb + slot * STAGE_B;
        int kb = kt * BK;
        const fp16* ga = Ax + (size_t)(m0 + a_row) * K + kb + (tid & 1) * 32;
        #pragma unroll
        for (int i = 0; i < 4; i++)
            cp16(st + a_sw[i], ga + i * 8);
        const fp16* gb = Bw + (size_t)(n0 + tid) * K + kb;
        #pragma unroll
        for (int j = 0; j < 8; j++)
            cp16(st + b_sw[j], gb + j * 8);
        cp_commit();
    };

    load_stage(0, 0);
    load_stage(1, 1);

    uint32_t af[2][4][4], bf[2][4][4];

    for (int kt = 0; kt < KT; kt++) {
        cp_wait1();
        __syncthreads();
        if (kt + 2 < KT) load_stage((kt + 2) % NSTAGE, kt + 2);

        uint32_t st = sb + (kt % NSTAGE) * STAGE_B;

        // prime substep 0
        {
            uint32_t ks = cb;
            #pragma unroll
            for (int g = 0; g < 4; g++) ldsm4(st + b_r[g] + (ks ^ b_x[g]), bf[0][g]);
            #pragma unroll
            for (int mi = 0; mi < 4; mi++) ldsm4(st + a_r[mi] + (ks ^ a_x[mi]), af[0][mi]);
        }
        #pragma unroll
        for (int s = 0; s < 4; s++) {
            int cur = s & 1, nxt = cur ^ 1;
            if (s < 3) {
                uint32_t ks = cb + (uint32_t)((s + 1) * 32);
                #pragma unroll
                for (int g = 0; g < 4; g++) ldsm4(st + b_r[g] + (ks ^ b_x[g]), bf[nxt][g]);
                #pragma unroll
                for (int mi = 0; mi < 4; mi++) ldsm4(st + a_r[mi] + (ks ^ a_x[mi]), af[nxt][mi]);
            }
            #pragma unroll
            for (int mi = 0; mi < 4; mi++) {
                #pragma unroll
                for (int ni = 0; ni < 8; ni++) {
                    int g = ni >> 1, sel = ni & 1;
                    mma16816(acc[mi][ni], af[cur][mi], bf[cur][g][sel], bf[cur][g][sel + 2]);
                }
            }
        }
    }

    // ---- epilogue ----
    int gid = lane >> 2, tig = lane & 3;
    #pragma unroll
    for (int mi = 0; mi < 4; mi++) {
        int row = m0 + warp_m + mi * 16 + gid;
        #pragma unroll
        for (int ni = 0; ni < 8; ni++) {
            int col = n0 + warp_n + ni * 8 + tig * 2;
            float bcol0 = __ldg(&bias[col]), bcol1 = __ldg(&bias[col + 1]);
            #pragma unroll
            for (int half = 0; half < 2; half++) {
                int rr = row + half * 8;
                float v0 = acc[mi][ni][half * 2 + 0] + bcol0;
                float v1 = acc[mi][ni][half * 2 + 1] + bcol1;
                if (MODE == 0) {
                    v0 = 0.5f * v0 * (1.0f + erff(v0 * 0.70710678118654752f));
                    v1 = 0.5f * v1 * (1.0f + erff(v1 * 0.70710678118654752f));
                    *(__half2*)(outH + (size_t)rr * N + col) = __floats2half2_rn(v0, v1);
                } else {
                    float2 v; v.x = v0; v.y = v1;
                    *(float2*)(outf + (size_t)rr * N + col) = v;
                }
            }
        }
    }
}

// ===========================================================================
extern "C" void kernel_launch(void* const* d_in, const int* in_sizes, int n_in,
                              void* d_out, int out_size) {
    const float* x      = (const float*)d_in[0];
    const float* W_fc   = (const float*)d_in[1];
    const float* b_fc   = (const float*)d_in[2];
    const float* A_fc   = (const float*)d_in[3];
    const float* B_fc   = (const float*)d_in[4];
    const float* W_proj = (const float*)d_in[5];
    const float* b_proj = (const float*)d_in[6];
    const float* A_proj = (const float*)d_in[7];
    const float* B_proj = (const float*)d_in[8];
    float* out = (float*)d_out;

    fp16 *x16, *wfc, *h16, *wp;
    cudaGetSymbolAddress((void**)&x16, g_x16);
    cudaGetSymbolAddress((void**)&wfc, g_wfc);
    cudaGetSymbolAddress((void**)&h16, g_h16);
    cudaGetSymbolAddress((void**)&wp,  g_wp);

    cudaFuncSetAttribute(k_gemm<0>, cudaFuncAttributeMaxDynamicSharedMemorySize, GSMEM);
    cudaFuncSetAttribute(k_gemm<1>, cudaFuncAttributeMaxDynamicSharedMemorySize, GSMEM);

    k_init_max<<<1, 32>>>();
    k_absmax2<<<dim3(128, 2), 256>>>(W_fc, W_proj);

    k_quant_w<<<dim3(D / 512, F), 256>>>(W_fc,   A_fc,   B_fc,   wfc, D, 0);
    k_quant_w<<<dim3(F / 512, D), 256>>>(W_proj, A_proj, B_proj, wp,  F, 1);
    k_convert_x<<<(MTOT * D / 4) / 256, 256>>>((const float4*)x, x16);

    // GEMM1: [8192,1024] x [4096,1024]^T -> GELU -> fp16 H
    k_gemm<0><<<dim3(F / 256, MTOT / 128), 256, GSMEM>>>(
        x16, wfc, b_fc, nullptr, h16, D, F);
    // GEMM2: [8192,4096] x [1024,4096]^T -> fp32 out
    k_gemm<1><<<dim3(D / 256, MTOT / 128), 256, GSMEM>>>(
        h16, wp, b_proj, out, nullptr, F, D);
}

// round 11
// speedup vs baseline: 1.1786x; 1.1786x over previous
#include <cuda_runtime.h>
#include <cuda_fp16.h>
#include <math.h>
#include <stdint.h>

#define D 1024
#define F 4096
#define MTOT 8192

typedef __half fp16;

// ---- scratch (static device globals: allocation-free) ----
__device__ fp16 g_x16[(size_t)MTOT * D];  // 16 MB
__device__ fp16 g_wfc[(size_t)F * D];     // 8 MB
__device__ fp16 g_h16[(size_t)MTOT * F];  // 64 MB
__device__ fp16 g_wp[(size_t)D * F];      // 8 MB
__device__ unsigned int g_max2[2];

// ===========================================================================
// helpers
// ===========================================================================
__device__ __forceinline__ uint32_t smem_u32(const void* p) {
    uint32_t a;
    asm("{ .reg .u64 t; cvta.to.shared.u64 t, %1; cvt.u32.u64 %0, t; }" : "=r"(a) : "l"(p));
    return a;
}
__device__ __forceinline__ void cp16(uint32_t s, const void* g) {
    asm volatile("cp.async.cg.shared.global [%0], [%1], 16;" :: "r"(s), "l"(g));
}
__device__ __forceinline__ void cp_commit() {
    asm volatile("cp.async.commit_group;");
}
__device__ __forceinline__ void cp_wait3() {
    asm volatile("cp.async.wait_group 3;");
}
__device__ __forceinline__ void ldsm4(uint32_t a, uint32_t& r0, uint32_t& r1,
                                      uint32_t& r2, uint32_t& r3) {
    asm volatile("ldmatrix.sync.aligned.m8n8.x4.shared.b16 {%0,%1,%2,%3}, [%4];"
                 : "=r"(r0), "=r"(r1), "=r"(r2), "=r"(r3) : "r"(a));
}
__device__ __forceinline__ void mma16816(float* c, const uint32_t* a, uint32_t b0, uint32_t b1) {
    asm volatile(
        "mma.sync.aligned.m16n8k16.row.col.f32.f16.f16.f32 "
        "{%0,%1,%2,%3}, {%4,%5,%6,%7}, {%8,%9}, {%0,%1,%2,%3};"
        : "+f"(c[0]), "+f"(c[1]), "+f"(c[2]), "+f"(c[3])
        : "r"(a[0]), "r"(a[1]), "r"(a[2]), "r"(a[3]), "r"(b0), "r"(b1));
}

// ===========================================================================
// pre-pass kernels
// ===========================================================================
__global__ void k_init_max() { g_max2[0] = 0u; g_max2[1] = 0u; }

// blockIdx.y selects tensor (0: W_fc, 1: W_proj); both are F*D floats.
__global__ void k_absmax2(const float* __restrict__ W0, const float* __restrict__ W1) {
    int sel = blockIdx.y;
    const float* W = sel ? W1 : W0;
    int n = F * D;
    float m = 0.f;
    int stride = gridDim.x * blockDim.x;
    for (int i = blockIdx.x * blockDim.x + threadIdx.x; i < n; i += stride)
        m = fmaxf(m, fabsf(W[i]));
    #pragma unroll
    for (int o = 16; o; o >>= 1) m = fmaxf(m, __shfl_xor_sync(0xffffffffu, m, o));
    __shared__ float sm[8];
    int lane = threadIdx.x & 31, w = threadIdx.x >> 5;
    if (lane == 0) sm[w] = m;
    __syncthreads();
    if (threadIdx.x == 0) {
        float mm = sm[0];
        for (int i = 1; i < 8; i++) mm = fmaxf(mm, sm[i]);
        atomicMax(&g_max2[sel], __float_as_uint(mm));
    }
}

// fakequant(W) + 2*B@A -> single fp16, row-major [out, K]
__global__ void k_quant_w(const float* __restrict__ W, const float* __restrict__ A,
                          const float* __restrict__ Bm, fp16* __restrict__ Wo,
                          int K, int sel) {
    int o = blockIdx.y;
    __shared__ float Bs[16];
    if (threadIdx.x < 16) Bs[threadIdx.x] = Bm[o * 16 + threadIdx.x];
    __syncthreads();
    float mx = __uint_as_float(g_max2[sel]);
    float scale = mx * (1.0f / 127.0f);
    float inv   = 127.0f / mx;
    int k = (blockIdx.x * blockDim.x + threadIdx.x) * 2;
    float w0 = W[(size_t)o * K + k], w1 = W[(size_t)o * K + k + 1];
    float q0 = fminf(fmaxf(rintf(w0 * inv), -128.f), 127.f) * scale;
    float q1 = fminf(fmaxf(rintf(w1 * inv), -128.f), 127.f) * scale;
    float a0 = 0.f, a1 = 0.f;
    #pragma unroll
    for (int r = 0; r < 16; r++) {
        a0 = fmaf(Bs[r], A[(size_t)r * K + k],     a0);
        a1 = fmaf(Bs[r], A[(size_t)r * K + k + 1], a1);
    }
    float v0 = q0 + 2.0f * a0, v1 = q1 + 2.0f * a1;
    *(__half2*)(Wo + (size_t)o * K + k) = __floats2half2_rn(v0, v1);
}

__global__ void k_convert_x(const float4* __restrict__ x, fp16* __restrict__ xo) {
    size_t i = (size_t)blockIdx.x * blockDim.x + threadIdx.x;
    float4 v = x[i];
    __half2* p = (__half2*)(xo + i * 4);
    p[0] = __floats2half2_rn(v.x, v.y);
    p[1] = __floats2half2_rn(v.z, v.w);
}

// ===========================================================================
// GEMM: C[M,N] = A[M,K] * B[N,K]^T + bias, pure fp16, fp32 accum
// CTA tile 128x256, BK=32, 5-stage cp.async pipeline, ONE barrier/iter
// 8 warps = 2(m) x 4(n), warp tile 64x64
// MODE 0: epilogue bias + exact GELU -> fp16 H (row-major)
// MODE 1: epilogue bias -> fp32 out
// ===========================================================================
#define BK 32
#define RSB 80                        // 64B data + 16B pad
#define MAT_A (128 * RSB)             // 10240
#define MAT_Bm (256 * RSB)            // 20480
#define STAGE_B (MAT_A + MAT_Bm)      // 30720
#define NSTAGE 5
#define GSMEM (NSTAGE * STAGE_B)      // 153600

template <int MODE>
__global__ void __launch_bounds__(256, 1)
k_gemm(const fp16* __restrict__ Ax, const fp16* __restrict__ Bw,
       const float* __restrict__ bias, float* __restrict__ outf,
       fp16* __restrict__ outH, int K, int N) {
    extern __shared__ char smem[];
    uint32_t sb = smem_u32(smem);
    int tid = threadIdx.x, wid = tid >> 5, lane = tid & 31;
    int m0 = blockIdx.y * 128;
    int n0 = blockIdx.x * 256;
    int warp_m = (wid >> 2) * 64;
    int warp_n = (wid & 3) * 64;

    int r0i = tid >> 2;               // base row 0..63
    int c0i = tid & 3;                // 16B chunk within 64B row

    float acc[4][8][4];
    #pragma unroll
    for (int i = 0; i < 4; i++)
        #pragma unroll
        for (int j = 0; j < 8; j++)
            #pragma unroll
            for (int q = 0; q < 4; q++) acc[i][j][q] = 0.f;

    int KT = K / BK;

    uint32_t a_off[4], b_off[4];
    #pragma unroll
    for (int mi = 0; mi < 4; mi++)
        a_off[mi] = (uint32_t)((warp_m + mi * 16 + (lane & 15)) * RSB + (lane >> 4) * 16);
    #pragma unroll
    for (int g = 0; g < 4; g++)
        b_off[g] = (uint32_t)(MAT_A + (warp_n + g * 16 + (lane & 15)) * RSB + (lane >> 4) * 16);

    auto load_stage = [&](int slot, int kt) {
        uint32_t st = sb + slot * STAGE_B;
        int kb = kt * BK;
        #pragma unroll
        for (int j = 0; j < 2; j++) {          // A: 128 rows
            int row = r0i + j * 64;
            cp16(st + (uint32_t)(row * RSB + c0i * 16),
                 Ax + (size_t)(m0 + row) * K + kb + c0i * 8);
        }
        #pragma unroll
        for (int j = 0; j < 4; j++) {          // B: 256 rows
            int row = r0i + j * 64;
            cp16(st + (uint32_t)(MAT_A + row * RSB + c0i * 16),
                 Bw + (size_t)(n0 + row) * K + kb + c0i * 8);
        }
        cp_commit();
    };

    load_stage(0, 0);
    load_stage(1, 1);
    load_stage(2, 2);
    load_stage(3, 3);

    for (int kt = 0; kt < KT; kt++) {
        cp_wait3();
        __syncthreads();
        if (kt + 4 < KT) load_stage((kt + 4) % NSTAGE, kt + 4);

        uint32_t st = sb + (kt % NSTAGE) * STAGE_B;
        #pragma unroll
        for (int s = 0; s < 2; s++) {
            uint32_t ks = s * 32;
            uint32_t af[4][4], bf[4][4];
            #pragma unroll
            for (int g = 0; g < 4; g++)
                ldsm4(st + b_off[g] + ks, bf[g][0], bf[g][1], bf[g][2], bf[g][3]);
            #pragma unroll
            for (int mi = 0; mi < 4; mi++)
                ldsm4(st + a_off[mi] + ks, af[mi][0], af[mi][1], af[mi][2], af[mi][3]);
            #pragma unroll
            for (int mi = 0; mi < 4; mi++) {
                #pragma unroll
                for (int ni = 0; ni < 8; ni++) {
                    int g = ni >> 1, sel = ni & 1;
                    mma16816(acc[mi][ni], af[mi], bf[g][sel], bf[g][sel + 2]);
                }
            }
        }
        // NOTE: no end-of-loop barrier. The next iteration's top barrier
        // orders all ldsm reads of slot (kt+5)%5 = kt%5 before its rewrite
        // (writes are issued only after that barrier).
    }

    // ---- epilogue ----
    int gid = lane >> 2, tig = lane & 3;
    #pragma unroll
    for (int mi = 0; mi < 4; mi++) {
        int row = m0 + warp_m + mi * 16 + gid;
        #pragma unroll
        for (int ni = 0; ni < 8; ni++) {
            int col = n0 + warp_n + ni * 8 + tig * 2;
            float bcol0 = __ldg(&bias[col]), bcol1 = __ldg(&bias[col + 1]);
            #pragma unroll
            for (int half = 0; half < 2; half++) {
                int rr = row + half * 8;
                float v0 = acc[mi][ni][half * 2 + 0] + bcol0;
                float v1 = acc[mi][ni][half * 2 + 1] + bcol1;
                if (MODE == 0) {
                    v0 = 0.5f * v0 * (1.0f + erff(v0 * 0.70710678118654752f));
                    v1 = 0.5f * v1 * (1.0f + erff(v1 * 0.70710678118654752f));
                    *(__half2*)(outH + (size_t)rr * N + col) = __floats2half2_rn(v0, v1);
                } else {
                    float2 v; v.x = v0; v.y = v1;
                    *(float2*)(outf + (size_t)rr * N + col) = v;
                }
            }
        }
    }
}

// ===========================================================================
extern "C" void kernel_launch(void* const* d_in, const int* in_sizes, int n_in,
                              void* d_out, int out_size) {
    const float* x      = (const float*)d_in[0];
    const float* W_fc   = (const float*)d_in[1];
    const float* b_fc   = (const float*)d_in[2];
    const float* A_fc   = (const float*)d_in[3];
    const float* B_fc   = (const float*)d_in[4];
    const float* W_proj = (const float*)d_in[5];
    const float* b_proj = (const float*)d_in[6];
    const float* A_proj = (const float*)d_in[7];
    const float* B_proj = (const float*)d_in[8];
    float* out = (float*)d_out;

    fp16 *x16, *wfc, *h16, *wp;
    cudaGetSymbolAddress((void**)&x16, g_x16);
    cudaGetSymbolAddress((void**)&wfc, g_wfc);
    cudaGetSymbolAddress((void**)&h16, g_h16);
    cudaGetSymbolAddress((void**)&wp,  g_wp);

    cudaFuncSetAttribute(k_gemm<0>, cudaFuncAttributeMaxDynamicSharedMemorySize, GSMEM);
    cudaFuncSetAttribute(k_gemm<1>, cudaFuncAttributeMaxDynamicSharedMemorySize, GSMEM);

    k_init_max<<<1, 32>>>();
    k_absmax2<<<dim3(128, 2), 256>>>(W_fc, W_proj);

    k_quant_w<<<dim3(D / 512, F), 256>>>(W_fc,   A_fc,   B_fc,   wfc, D, 0);
    k_quant_w<<<dim3(F / 512, D), 256>>>(W_proj, A_proj, B_proj, wp,  F, 1);
    k_convert_x<<<(MTOT * D / 4) / 256, 256>>>((const float4*)x, x16);

    // GEMM1: [8192,1024] x [4096,1024]^T -> GELU -> fp16 H
    k_gemm<0><<<dim3(F / 256, MTOT / 128), 256, GSMEM>>>(
        x16, wfc, b_fc, nullptr, h16, D, F);
    // GEMM2: [8192,4096] x [1024,4096]^T -> fp32 out
    k_gemm<1><<<dim3(D / 256, MTOT / 128), 256, GSMEM>>>(
        h16, wp, b_proj, out, nullptr, F, D);
}